// round 5
// baseline (speedup 1.0000x reference)
#include <cuda_runtime.h>
#include <math.h>

// Problem constants: N=4, R=16384, K=96
#define KS   96
#define KM   95                 // K-1 midpoint samples
#define RAYS (4 * 16384)        // 65536 rays

#define FULL  0xffffffffu
#define LOG2E 1.4426950408889634f

__device__ __forceinline__ float ex2f(float x) {
    float r;
    asm("ex2.approx.ftz.f32 %0, %1;" : "=f"(r) : "f"(x));
    return r;
}
__device__ __forceinline__ float lg2f(float x) {
    float r;
    asm("lg2.approx.ftz.f32 %0, %1;" : "=f"(r) : "f"(x));
    return r;
}

// One warp per ray; 3 chunks of 32 lanes cover samples i = 0..95.
//  - Neighbors (d[i+1], s[i+1]) come from direct (L1-hitting) loads, front-
//    batched with everything else: zero shuffles before the scan.
//  - The 3 chunk scans are INDEPENDENT and run interleaved (ILP=3); chunk
//    coupling is applied afterwards via chunk-total products.
//  - Midpoint identity: sum_i w_i*0.5*(x_i+x_{i+1}) = 0.5*sum_j x_j*(w_j+w_{j-1});
//    final rgb = (0.5*S)*2 - 1 = S - 1.
//  - Global depth clip + NaN path are provable no-ops (convex combination of
//    the ray's own midpoints; wsum > 0 since softplus > 0, sorted deltas > 0).
__global__ void __launch_bounds__(256) render_kernel(
    const float* __restrict__ rgbs,     // [RAYS, K, 3]
    const float* __restrict__ sigmas,   // [RAYS, K]
    const float* __restrict__ depths,   // [RAYS, K]
    float* __restrict__ out_rgb,        // [RAYS, 3]
    float* __restrict__ out_depth,      // [RAYS]
    float* __restrict__ out_w)          // [RAYS, KM]
{
    int warp = (blockIdx.x * blockDim.x + threadIdx.x) >> 5;
    int lane = threadIdx.x & 31;
    if (warp >= RAYS) return;

    const float* d  = depths + (size_t)warp * KS;
    const float* s  = sigmas + (size_t)warp * KS;
    const float* rg = rgbs   + (size_t)warp * KS * 3;
    float* wout     = out_w  + (size_t)warp * KM;

    // Front-batched loads (21 independent LDGs -> max MLP).
    float dv[3], d1[3], sv[3], s1[3], rx[3], ry[3], rz[3];
    #pragma unroll
    for (int c = 0; c < 3; ++c) {
        int i  = c * 32 + lane;
        int i1 = (i + 1 < KS) ? i + 1 : KS - 1;   // clamp (i==95 masked later)
        dv[c] = d[i];   d1[c] = d[i1];
        sv[c] = s[i];   s1[c] = s[i1];
        rx[c] = rg[3 * i + 0];
        ry[c] = rg[3 * i + 1];
        rz[c] = rg[3 * i + 2];
    }

    // Per-chunk alpha and scan input t (shuffle-free).
    float alpha[3], p[3];
    #pragma unroll
    for (int c = 0; c < 3; ++c) {
        bool valid = (c < 2) | (lane < 31);           // only i==95 invalid
        float delta = d1[c] - dv[c];
        float sm    = 0.5f * (sv[c] + s1[c]) - 1.0f;
        // softplus(sm) * log2e, stable fast form via MUFU ex2/lg2
        float em    = ex2f(-fabsf(sm) * LOG2E);
        float L     = fmaxf(sm, 0.0f) * LOG2E + lg2f(1.0f + em);
        alpha[c]    = 1.0f - ex2f(-delta * L);
        p[c]        = valid ? (1.0f - alpha[c] + 1e-10f) : 1.0f;
    }

    // Three independent inclusive multiplicative scans, interleaved (ILP=3).
    #pragma unroll
    for (int off = 1; off < 32; off <<= 1) {
        float v0 = __shfl_up_sync(FULL, p[0], off);
        float v1 = __shfl_up_sync(FULL, p[1], off);
        float v2 = __shfl_up_sync(FULL, p[2], off);
        if (lane >= off) { p[0] *= v0; p[1] *= v1; p[2] *= v2; }
    }

    // Exclusive per chunk + cross-chunk combine via chunk totals.
    float e0 = __shfl_up_sync(FULL, p[0], 1);
    float e1 = __shfl_up_sync(FULL, p[1], 1);
    float e2 = __shfl_up_sync(FULL, p[2], 1);
    if (lane == 0) { e0 = 1.0f; e1 = 1.0f; e2 = 1.0f; }
    float T0 = __shfl_sync(FULL, p[0], 31);
    float T1 = __shfl_sync(FULL, p[1], 31);

    float w0 = alpha[0] * e0;
    float w1 = alpha[1] * (T0 * e1);
    float w2 = alpha[2] * (T0 * T1 * e2);
    if (lane == 31) w2 = 0.0f;                        // i==95 invalid

    // Store weights (coalesced, 1 line per STG).
    wout[lane]      = w0;
    wout[32 + lane] = w1;
    if (lane < 31) wout[64 + lane] = w2;

    // w_{j-1} chain for the midpoint identity.
    float wp0 = __shfl_up_sync(FULL, w0, 1);
    float wp1 = __shfl_up_sync(FULL, w1, 1);
    float wp2 = __shfl_up_sync(FULL, w2, 1);
    float b0  = __shfl_sync(FULL, w0, 31);
    float b1  = __shfl_sync(FULL, w1, 31);
    if (lane == 0) { wp0 = 0.0f; wp1 = b0; wp2 = b1; }

    float ww0 = w0 + wp0, ww1 = w1 + wp1, ww2 = w2 + wp2;
    float wsum = w0 + w1 + w2;
    float ar = ww0 * rx[0], ag = ww0 * ry[0], ab = ww0 * rz[0], ad = ww0 * dv[0];
    ar = fmaf(ww1, rx[1], ar); ag = fmaf(ww1, ry[1], ag);
    ab = fmaf(ww1, rz[1], ab); ad = fmaf(ww1, dv[1], ad);
    ar = fmaf(ww2, rx[2], ar); ag = fmaf(ww2, ry[2], ag);
    ab = fmaf(ww2, rz[2], ab); ad = fmaf(ww2, dv[2], ad);

    // Warp reduction of the 5 accumulators.
    #pragma unroll
    for (int off = 16; off; off >>= 1) {
        wsum += __shfl_down_sync(FULL, wsum, off);
        ar   += __shfl_down_sync(FULL, ar,   off);
        ag   += __shfl_down_sync(FULL, ag,   off);
        ab   += __shfl_down_sync(FULL, ab,   off);
        ad   += __shfl_down_sync(FULL, ad,   off);
    }

    if (lane == 0) {
        out_rgb[warp * 3 + 0] = ar - 1.0f;       // (0.5*ar)*2 - 1
        out_rgb[warp * 3 + 1] = ag - 1.0f;
        out_rgb[warp * 3 + 2] = ab - 1.0f;
        out_depth[warp] = (0.5f * ad) / wsum;    // clip/NaN path: no-op
    }
}

extern "C" void kernel_launch(void* const* d_in, const int* in_sizes, int n_in,
                              void* d_out, int out_size) {
    const float* rgbs   = (const float*)d_in[0];
    const float* sigmas = (const float*)d_in[1];
    const float* depths = (const float*)d_in[2];

    float* out = (float*)d_out;
    float* out_rgb   = out;                       // 65536*3
    float* out_depth = out + (size_t)RAYS * 3;    // 65536
    float* out_w     = out + (size_t)RAYS * 4;    // 65536*95

    int blocks = (RAYS + 7) / 8;                  // one warp per ray
    render_kernel<<<blocks, 256>>>(rgbs, sigmas, depths, out_rgb, out_depth, out_w);
}